// round 16
// baseline (speedup 1.0000x reference)
#include <cuda_runtime.h>

#define NN     100000
#define NE     3200000
#define BGR    64
#define DIM    16
#define NFP    33
#define EMBD   128
#define LG     3000
#define LL     2998
#define NFILT  32
#define FCIN   3872    // 32*121
#define TMAX   65
#define NBSC   98      // scan blocks: 98*1024 >= NN+1
#define FULL   0xffffffffu
#define INVW   (1.0f / 32767.0f)

// ---------------- device scratch (static, no allocation) ----------------
__device__ int      g_off[NN + 1];
__device__ int      g_cur[NN];
__device__ unsigned g_csru[NE];          // (src << 15) | w_q15
__device__ float4   g_pxp[NN * 9];       // padded 36-float rows of pro_x
__device__ float4   g_xb0[NN * 4];       // hidden x fp32 (16 floats per node)
__device__ float4   g_xb1[NN * 4];
__device__ double   g_stats5[5 * 32];    // per-layer: [0:16) sum, [16:32) sumsq
__device__ float    g_pool[BGR * DIM];
__device__ int      g_bsum[NBSC];
__device__ int      g_bpref[NBSC];
__device__ int      g_arrive;
__device__ int      g_ready;
__device__ int      g_boffG[BGR * (TMAX + 1)];
__device__ int      g_boffL[BGR * (TMAX + 1)];
__device__ int      g_blistG[BGR * LG];
__device__ int      g_blistL[BGR * LL];
__device__ float    g_wtG[BGR * NFILT * 5 * 8];
__device__ float    g_wtL[BGR * NFILT * TMAX * 8];
__device__ float    g_yG[BGR * FCIN];
__device__ float    g_yL[BGR * FCIN];

// ---------------- init (scalars/stats/pool only; g_off zeroed via memset) ----------------
__global__ void k_initB() {
    int i = threadIdx.x;
    for (int j = i; j < 5 * 32; j += 256) g_stats5[j] = 0.0;
    if (i == 0) { g_arrive = 0; g_ready = 0; }
    for (int j = i; j < BGR * DIM; j += 256) g_pool[j] = 0.f;
}

// ---------------- pad pro_x to 36-float rows + degree histogram, fused ----------------
__global__ void k_padhist(const float* __restrict__ px, const int* __restrict__ ei) {
    int i  = blockIdx.x * blockDim.x + threadIdx.x;
    int st = gridDim.x * blockDim.x;
    float* o = (float*)g_pxp;
    for (int idx = i; idx < NN * 36; idx += st) {
        int n = idx / 36, d = idx - n * 36;
        o[idx] = (d < NFP) ? px[n * NFP + d] : 0.f;
    }
    for (int e = i; e < NE; e += st) atomicAdd(&g_off[ei[NE + e] + 1], 1);
}

// ---------------- single-pass decoupled scan (98 blocks, warp-parallel tail) ----------------
__global__ void k_scanAll() {
    __shared__ int s[1024];
    __shared__ int bpref;
    int t = threadIdx.x;
    int i = blockIdx.x * 1024 + t;
    int v = (i <= NN) ? g_off[i] : 0;
    s[t] = v;
    __syncthreads();
    for (int ofs = 1; ofs < 1024; ofs <<= 1) {
        int add = (t >= ofs) ? s[t - ofs] : 0;
        __syncthreads();
        s[t] += add;
        __syncthreads();
    }
    int myinc = s[t];
    if (t < 32) {
        int ticket = 0;
        if (t == 0) {
            g_bsum[blockIdx.x] = s[1023];
            __threadfence();
            ticket = atomicAdd(&g_arrive, 1);
        }
        ticket = __shfl_sync(FULL, ticket, 0);
        if (ticket == NBSC - 1) {
            int b0 = t * 4;
            int v0 = (b0     < NBSC) ? __ldcg(&g_bsum[b0])     : 0;
            int v1 = (b0 + 1 < NBSC) ? __ldcg(&g_bsum[b0 + 1]) : 0;
            int v2 = (b0 + 2 < NBSC) ? __ldcg(&g_bsum[b0 + 2]) : 0;
            int v3 = (b0 + 3 < NBSC) ? __ldcg(&g_bsum[b0 + 3]) : 0;
            int lsum = v0 + v1 + v2 + v3;
            int pre = lsum;
            #pragma unroll
            for (int ofs = 1; ofs < 32; ofs <<= 1) {
                int up = __shfl_up_sync(FULL, pre, ofs);
                if (t >= ofs) pre += up;
            }
            pre -= lsum;   // exclusive
            if (b0     < NBSC) g_bpref[b0]     = pre;
            if (b0 + 1 < NBSC) g_bpref[b0 + 1] = pre + v0;
            if (b0 + 2 < NBSC) g_bpref[b0 + 2] = pre + v0 + v1;
            if (b0 + 3 < NBSC) g_bpref[b0 + 3] = pre + v0 + v1 + v2;
            __threadfence();
            if (t == 0) atomicExch(&g_ready, 1);
        }
        if (t == 0) {
            while (atomicAdd(&g_ready, 0) == 0) { __nanosleep(64); }
            bpref = __ldcg(&g_bpref[blockIdx.x]);
        }
    }
    __syncthreads();
    if (i <= NN) {
        int fin = myinc + bpref;
        g_off[i] = fin;
        if (i < NN) g_cur[i] = fin;
    }
}

// ---------------- scatter (L2 throughput floor; ILP2) ----------------
__global__ void k_scatter(const int* __restrict__ ei, const float* __restrict__ pw) {
    int i  = blockIdx.x * blockDim.x + threadIdx.x;
    int st = gridDim.x * blockDim.x;
    for (int e = i * 2; e < NE; e += st * 2) {
        int s0 = ei[e],      d0 = ei[NE + e];
        int s1 = ei[e + 1],  d1 = ei[NE + e + 1];
        float w0v = pw[e], w1v = pw[e + 1];
        unsigned q0 = (unsigned)(w0v * 32767.0f + 0.5f);
        unsigned q1 = (unsigned)(w1v * 32767.0f + 0.5f);
        int p0 = atomicAdd(&g_cur[d0], 1);
        int p1 = atomicAdd(&g_cur[d1], 1);
        g_csru[p0] = ((unsigned)s0 << 15) | q0;
        g_csru[p1] = ((unsigned)s1 << 15) | q1;
    }
}

// ---------------- GINE layer 1 (33 -> 16): trip-count loop + split-half MLP (dual acc) ----------------
__global__ void k_gine33(const float* __restrict__ W1, const float* __restrict__ b1,
                         const float* __restrict__ W2, const float* __restrict__ b2,
                         const float* __restrict__ ew, const float* __restrict__ ebv,
                         const float* __restrict__ epsp) {
    __shared__ float sW1[NFP * 16], sW2[256], sb1[16], sb2[16], sc[36], se[36];
    __shared__ float ssum[16], ssq[16];
    int t = threadIdx.x;
    for (int i = t; i < NFP * 16; i += 256) sW1[i] = W1[i];
    for (int i = t; i < 256; i += 256) sW2[i] = W2[i];
    if (t < 16) { sb1[t] = b1[t]; sb2[t] = b2[t]; ssum[t] = 0.f; ssq[t] = 0.f; }
    if (t < 36) { sc[t] = (t < NFP) ? ew[t] : 0.f; se[t] = (t < NFP) ? ebv[t] : 0.f; }
    __syncthreads();
    float ope = 1.f + epsp[0];
    int lane  = t & 31;
    int eslot = lane >> 2, q = lane & 3;
    float cA0 = sc[q*4+0], cA1 = sc[q*4+1], cA2 = sc[q*4+2], cA3 = sc[q*4+3];
    float eA0 = se[q*4+0], eA1 = se[q*4+1], eA2 = se[q*4+2], eA3 = se[q*4+3];
    float cB0 = sc[(q+4)*4+0], cB1 = sc[(q+4)*4+1], cB2 = sc[(q+4)*4+2], cB3 = sc[(q+4)*4+3];
    float eB0 = se[(q+4)*4+0], eB1 = se[(q+4)*4+1], eB2 = se[(q+4)*4+2], eB3 = se[(q+4)*4+3];
    float c32 = sc[32], e32 = se[32];
    int gw = blockIdx.x * 8 + (t >> 5);
    int nw = gridDim.x * 8;
    float lsum = 0.f, lsq = 0.f;
    for (int n = gw; n < NN; n += nw) {
        int beg = g_off[n], end = g_off[n + 1];
        int trips = (end - beg + 7) >> 3;   // warp-uniform
        const float* nrow = (const float*)(g_pxp + n * 9);
        float selfv = __ldg(nrow + lane);
        float self32 = __ldg(nrow + 32);
        float ax=0,ay=0,az=0,aw=0, bx=0,by=0,bz=0,bw=0, a32=0;
        int j = beg + eslot;
        unsigned vc0 = (j < end)     ? __ldg(&g_csru[j])     : 0u;
        unsigned vc1 = (j + 8 < end) ? __ldg(&g_csru[j + 8]) : 0u;
        float4 xa0 = make_float4(0, 0, 0, 0), xb0 = make_float4(0, 0, 0, 0);
        float x320 = 0.f;
        if (j < end) {
            const float4* row = g_pxp + (vc0 >> 15) * 9;
            xa0 = __ldg(row + q);
            xb0 = __ldg(row + q + 4);
            if (q == 0) x320 = __ldg(((const float*)row) + 32);
        }
        for (int it = 0; it < trips; it++) {
            unsigned vc2 = (j + 16 < end) ? __ldg(&g_csru[j + 16]) : 0u;
            float4 xa1 = make_float4(0, 0, 0, 0), xb1 = make_float4(0, 0, 0, 0);
            float x321 = 0.f;
            if (j + 8 < end) {
                const float4* row = g_pxp + (vc1 >> 15) * 9;
                xa1 = __ldg(row + q);
                xb1 = __ldg(row + q + 4);
                if (q == 0) x321 = __ldg(((const float*)row) + 32);
            }
            if (j < end) {
                float wv = (float)(vc0 & 32767u) * INVW;
                ax += fmaxf(xa0.x + fmaf(wv, cA0, eA0), 0.f);
                ay += fmaxf(xa0.y + fmaf(wv, cA1, eA1), 0.f);
                az += fmaxf(xa0.z + fmaf(wv, cA2, eA2), 0.f);
                aw += fmaxf(xa0.w + fmaf(wv, cA3, eA3), 0.f);
                bx += fmaxf(xb0.x + fmaf(wv, cB0, eB0), 0.f);
                by += fmaxf(xb0.y + fmaf(wv, cB1, eB1), 0.f);
                bz += fmaxf(xb0.z + fmaf(wv, cB2, eB2), 0.f);
                bw += fmaxf(xb0.w + fmaf(wv, cB3, eB3), 0.f);
                if (q == 0) a32 += fmaxf(x320 + fmaf(wv, c32, e32), 0.f);
            }
            vc0 = vc1; vc1 = vc2;
            xa0 = xa1; xb0 = xb1; x320 = x321;
            j += 8;
        }
        #pragma unroll
        for (int ofs = 4; ofs < 32; ofs <<= 1) {
            ax += __shfl_xor_sync(FULL, ax, ofs); ay += __shfl_xor_sync(FULL, ay, ofs);
            az += __shfl_xor_sync(FULL, az, ofs); aw += __shfl_xor_sync(FULL, aw, ofs);
            bx += __shfl_xor_sync(FULL, bx, ofs); by += __shfl_xor_sync(FULL, by, ofs);
            bz += __shfl_xor_sync(FULL, bz, ofs); bw += __shfl_xor_sync(FULL, bw, ofs);
            a32 += __shfl_xor_sync(FULL, a32, ofs);
        }
        int srcl = (lane >> 2) & 3;
        float vax = __shfl_sync(FULL, ax, srcl), vay = __shfl_sync(FULL, ay, srcl);
        float vaz = __shfl_sync(FULL, az, srcl), vaw = __shfl_sync(FULL, aw, srcl);
        float vbx = __shfl_sync(FULL, bx, srcl), vby = __shfl_sync(FULL, by, srcl);
        float vbz = __shfl_sync(FULL, bz, srcl), vbw = __shfl_sync(FULL, bw, srcl);
        float gx = (lane >= 16) ? vbx : vax;
        float gy = (lane >= 16) ? vby : vay;
        float gz = (lane >= 16) ? vbz : vaz;
        float gwv = (lane >= 16) ? vbw : vaw;
        float lo = (lane & 1) ? gy : gx;
        float hi = (lane & 1) ? gwv : gz;
        float aggv = (lane & 2) ? hi : lo;
        float agg32 = __shfl_sync(FULL, a32, 0);
        float h   = ope * selfv + aggv;    // dims 0..31 (lane = dim)
        float h32 = ope * self32 + agg32;
        // ---- split-half MLP, dual accumulators ----
        int o = lane & 15;
        int halfsel = lane & 16;
        int dbase = halfsel;
        float tj0 = halfsel ? (h32 * sW1[512 + o]) : sb1[o];
        float tj1 = 0.f;
        #pragma unroll
        for (int d = 0; d < 8; d++) {
            float hd0 = __shfl_sync(FULL, h, dbase + d);
            float hd1 = __shfl_sync(FULL, h, dbase + 8 + d);
            tj0 = fmaf(hd0, sW1[(dbase + d) * 16 + o], tj0);
            tj1 = fmaf(hd1, sW1[(dbase + 8 + d) * 16 + o], tj1);
        }
        float tj = tj0 + tj1;
        tj += __shfl_xor_sync(FULL, tj, 16);
        tj = fmaxf(tj, 0.f);
        int kbase = halfsel ? 8 : 0;
        float oj0 = halfsel ? 0.f : sb2[o];
        float oj1 = 0.f;
        #pragma unroll
        for (int k = 0; k < 4; k++) {
            float td0 = __shfl_sync(FULL, tj, kbase + k);
            float td1 = __shfl_sync(FULL, tj, kbase + 4 + k);
            oj0 = fmaf(td0, sW2[(kbase + k) * 16 + o], oj0);
            oj1 = fmaf(td1, sW2[(kbase + 4 + k) * 16 + o], oj1);
        }
        float oj = oj0 + oj1;
        oj += __shfl_xor_sync(FULL, oj, 16);
        if (lane < 16) {
            float y = fmaxf(oj, 0.f);
            ((float*)g_xb0)[n * DIM + lane] = y;
            lsum += y; lsq += y * y;
        }
    }
    if (lane < 16) { atomicAdd(&ssum[lane], lsum); atomicAdd(&ssq[lane], lsq); }
    __syncthreads();
    if (t < 16) {
        atomicAdd(&g_stats5[t],      (double)ssum[t]);
        atomicAdd(&g_stats5[16 + t], (double)ssq[t]);
    }
}

// ---------------- GINE layers 2..5: 2 nodes/warp, TWO edge chains per lane (MLP 4) ----------------
__global__ void __launch_bounds__(256, 4)
k_gine16(const float* __restrict__ W1, const float* __restrict__ b1,
         const float* __restrict__ W2, const float* __restrict__ b2,
         const float* __restrict__ ew, const float* __restrict__ ebv,
         const float* __restrict__ epsp,
         const float* __restrict__ gamma, const float* __restrict__ beta,
         const int* __restrict__ batch,
         int layer, int flip, int accpool) {
    const float4* xin4 = flip ? g_xb1 : g_xb0;
    float*        xout = (float*)(flip ? g_xb0 : g_xb1);
    const float*  xin  = (const float*)xin4;
    __shared__ float sW1[256], sW2[256], sb1[16], sb2[16], sc[16], se[16], sa[16], sbb[16];
    __shared__ float ssum[16], ssq[16];
    __shared__ float spool[BGR * DIM];
    int t = threadIdx.x;
    for (int i = t; i < 256; i += 256) { sW1[i] = W1[i]; sW2[i] = W2[i]; }
    if (accpool)
        for (int i = t; i < BGR * DIM; i += 256) spool[i] = 0.f;
    if (t < 16) {
        sb1[t] = b1[t]; sb2[t] = b2[t]; sc[t] = ew[t]; se[t] = ebv[t];
        double s = g_stats5[(layer - 1) * 32 + t], qd = g_stats5[(layer - 1) * 32 + 16 + t];
        float mu  = (float)(s / (double)NN);
        float var = (float)(qd / (double)NN) - mu * mu;
        float a   = gamma[t] * rsqrtf(fmaxf(var, 0.f) + 1e-5f);
        sa[t] = a; sbb[t] = beta[t] - mu * a;
        ssum[t] = 0.f; ssq[t] = 0.f;
    }
    __syncthreads();
    float ope = 1.f + epsp[0];
    int lane  = t & 31;
    int l16   = lane & 15;
    int hw    = lane >> 4;
    int hwb   = lane & 16;
    int eslot = l16 >> 2, q = l16 & 3;
    float a0 = sa[q*4+0], a1 = sa[q*4+1], a2 = sa[q*4+2], a3 = sa[q*4+3];
    float p0 = sbb[q*4+0], p1 = sbb[q*4+1], p2 = sbb[q*4+2], p3 = sbb[q*4+3];
    float c0 = sc[q*4+0], c1 = sc[q*4+1], c2 = sc[q*4+2], c3 = sc[q*4+3];
    float e0 = se[q*4+0], e1 = se[q*4+1], e2 = se[q*4+2], e3 = se[q*4+3];
    int gw = blockIdx.x * 8 + (t >> 5);
    int np = gridDim.x * 8;
    float lsum = 0.f, lsq = 0.f;
    for (int p = gw; p < NN / 2; p += np) {
        int n = p * 2 + hw;
        int beg = g_off[n], end = g_off[n + 1];
        int deg = end - beg;
        int degmax = max(deg, __shfl_xor_sync(FULL, deg, 16));
        int trips = (degmax + 7) >> 3;      // warp-uniform, 8 edges/node/iter
        float xn = __ldg(&xin[n * DIM + l16]);   // prefetch self
        float ax = 0.f, ay = 0.f, az = 0.f, aw = 0.f;
        int j = beg + eslot;                // chain A: j, chain B: j+4, stride 8
        unsigned vA0 = (j < end)      ? __ldg(&g_csru[j])      : 0u;
        unsigned vB0 = (j + 4 < end)  ? __ldg(&g_csru[j + 4])  : 0u;
        unsigned vA1 = (j + 8 < end)  ? __ldg(&g_csru[j + 8])  : 0u;
        unsigned vB1 = (j + 12 < end) ? __ldg(&g_csru[j + 12]) : 0u;
        float4 xA0 = make_float4(0, 0, 0, 0), xB0 = make_float4(0, 0, 0, 0);
        if (j < end)     xA0 = __ldg(&xin4[(vA0 >> 15) * 4 + q]);
        if (j + 4 < end) xB0 = __ldg(&xin4[(vB0 >> 15) * 4 + q]);
        for (int it = 0; it < trips; it++) {
            unsigned vA2 = (j + 16 < end) ? __ldg(&g_csru[j + 16]) : 0u;
            unsigned vB2 = (j + 20 < end) ? __ldg(&g_csru[j + 20]) : 0u;
            float4 xA1 = make_float4(0, 0, 0, 0), xB1 = make_float4(0, 0, 0, 0);
            if (j + 8 < end)  xA1 = __ldg(&xin4[(vA1 >> 15) * 4 + q]);
            if (j + 12 < end) xB1 = __ldg(&xin4[(vB1 >> 15) * 4 + q]);
            if (j < end) {
                float wv = (float)(vA0 & 32767u) * INVW;
                ax += fmaxf(fmaf(a0, xA0.x, p0) + fmaf(wv, c0, e0), 0.f);
                ay += fmaxf(fmaf(a1, xA0.y, p1) + fmaf(wv, c1, e1), 0.f);
                az += fmaxf(fmaf(a2, xA0.z, p2) + fmaf(wv, c2, e2), 0.f);
                aw += fmaxf(fmaf(a3, xA0.w, p3) + fmaf(wv, c3, e3), 0.f);
            }
            if (j + 4 < end) {
                float wv = (float)(vB0 & 32767u) * INVW;
                ax += fmaxf(fmaf(a0, xB0.x, p0) + fmaf(wv, c0, e0), 0.f);
                ay += fmaxf(fmaf(a1, xB0.y, p1) + fmaf(wv, c1, e1), 0.f);
                az += fmaxf(fmaf(a2, xB0.z, p2) + fmaf(wv, c2, e2), 0.f);
                aw += fmaxf(fmaf(a3, xB0.w, p3) + fmaf(wv, c3, e3), 0.f);
            }
            vA0 = vA1; vA1 = vA2; xA0 = xA1;
            vB0 = vB1; vB1 = vB2; xB0 = xB1;
            j += 8;
        }
        #pragma unroll
        for (int ofs = 4; ofs < 16; ofs <<= 1) {
            ax += __shfl_xor_sync(FULL, ax, ofs); ay += __shfl_xor_sync(FULL, ay, ofs);
            az += __shfl_xor_sync(FULL, az, ofs); aw += __shfl_xor_sync(FULL, aw, ofs);
        }
        int srcl = hwb + (l16 >> 2);
        float vx = __shfl_sync(FULL, ax, srcl);
        float vy = __shfl_sync(FULL, ay, srcl);
        float vz = __shfl_sync(FULL, az, srcl);
        float vw = __shfl_sync(FULL, aw, srcl);
        float lo = (l16 & 1) ? vy : vx;
        float hi = (l16 & 1) ? vw : vz;
        float aggv = (l16 & 2) ? hi : lo;
        float h = ope * fmaf(sa[l16], xn, sbb[l16]) + aggv;
        float tj0 = sb1[l16], tj1 = 0.f;
        #pragma unroll
        for (int dd = 0; dd < 8; dd++) {
            float hd0 = __shfl_sync(FULL, h, hwb + dd);
            float hd1 = __shfl_sync(FULL, h, hwb + 8 + dd);
            tj0 = fmaf(hd0, sW1[dd * 16 + l16], tj0);
            tj1 = fmaf(hd1, sW1[(8 + dd) * 16 + l16], tj1);
        }
        float tj = fmaxf(tj0 + tj1, 0.f);
        float oj0 = sb2[l16], oj1 = 0.f;
        #pragma unroll
        for (int dd = 0; dd < 8; dd++) {
            float td0 = __shfl_sync(FULL, tj, hwb + dd);
            float td1 = __shfl_sync(FULL, tj, hwb + 8 + dd);
            oj0 = fmaf(td0, sW2[dd * 16 + l16], oj0);
            oj1 = fmaf(td1, sW2[(8 + dd) * 16 + l16], oj1);
        }
        float y = fmaxf(oj0 + oj1, 0.f);
        if (accpool) {
            int bt = __ldg(&batch[n]);
            atomicAdd(&spool[bt * DIM + l16], y);
        } else {
            xout[n * DIM + l16] = y;
        }
        lsum += y; lsq += y * y;
    }
    atomicAdd(&ssum[l16], lsum); atomicAdd(&ssq[l16], lsq);
    __syncthreads();
    if (t < 16) {
        atomicAdd(&g_stats5[layer * 32 + t],      (double)ssum[t]);
        atomicAdd(&g_stats5[layer * 32 + 16 + t], (double)ssq[t]);
    }
    if (accpool)
        for (int i = t; i < BGR * DIM; i += 256) atomicAdd(&g_pool[i], spool[i]);
}

__device__ __forceinline__ int lbound(const int* a, int n, int key) {
    int lo = 0, hi = n;
    while (lo < hi) { int mid = (lo + hi) >> 1; if (a[mid] < key) lo = mid + 1; else hi = mid; }
    return lo;
}

// ---------------- head: final BN affine + mean + fc1_xp ----------------
__global__ void k_head(const int* __restrict__ batch,
                       const float* __restrict__ gamma, const float* __restrict__ beta,
                       const float* __restrict__ fw, const float* __restrict__ fb,
                       float* __restrict__ out) {
    __shared__ float sm[16];
    __shared__ int scnt;
    int b = blockIdx.x, t = threadIdx.x;
    if (t == 0) {
        int lo = lbound(batch, NN, b);
        int hi = lbound(batch, NN, b + 1);
        scnt = max(hi - lo, 1);
    }
    __syncthreads();
    if (t < 16) {
        double s = g_stats5[4 * 32 + t], qd = g_stats5[4 * 32 + 16 + t];
        float mu  = (float)(s / (double)NN);
        float var = (float)(qd / (double)NN) - mu * mu;
        float a   = gamma[t] * rsqrtf(fmaxf(var, 0.f) + 1e-5f);
        float bb  = beta[t] - mu * a;
        sm[t] = a * (g_pool[b * DIM + t] / (float)scnt) + bb;
    }
    __syncthreads();
    float acc = fb[t];
    #pragma unroll
    for (int dd = 0; dd < 16; dd++) acc += sm[dd] * fw[dd * EMBD + t];
    out[BGR * EMBD + b * EMBD + t] = fmaxf(acc, 0.f);
}

// ---------------- RNA: bucket build (fused G+L) + fc bias init ----------------
__global__ void k_bucket2(const int* __restrict__ tokG, const int* __restrict__ tokL,
                          const float* __restrict__ fb, float* __restrict__ out) {
    __shared__ int cnt[TMAX + 1];
    __shared__ int offs[TMAX + 1];
    int isL = blockIdx.x >> 6;
    int b   = blockIdx.x & 63;
    int L = isL ? LL : LG;
    int T = isL ? TMAX : 5;
    const int* tok  = isL ? tokL : tokG;
    int* list = isL ? g_blistL : g_blistG;
    int* boff = isL ? g_boffL  : g_boffG;
    int t = threadIdx.x;
    if (!isL && t < EMBD) out[b * EMBD + t] = fb[t];   // fc bias init
    if (t <= T) cnt[t] = 0;
    __syncthreads();
    const int* tb = tok + b * L;
    for (int c = t; c < L; c += 256) atomicAdd(&cnt[tb[c]], 1);
    __syncthreads();
    if (t == 0) {
        int acc = 0;
        for (int i = 0; i < T; i++) { offs[i] = acc; acc += cnt[i]; }
        offs[T] = acc;
    }
    __syncthreads();
    if (t <= T) boff[b * (TMAX + 1) + t] = offs[t];
    if (t < T) cnt[t] = offs[t];
    __syncthreads();
    for (int c = t; c < L; c += 256) {
        int pos = atomicAdd(&cnt[tb[c]], 1);
        list[b * L + pos] = c << 3;
    }
}

// ---------------- RNA: W~ gather-sum (fused G+L) ----------------
__global__ void k_wtilde4(const float* __restrict__ wG, const float* __restrict__ wL) {
    __shared__ int soff[TMAX + 1];
    int isL = blockIdx.x < 2048 ? 1 : 0;
    int bf  = isL ? blockIdx.x : (blockIdx.x - 2048);
    int b = bf >> 5, f = bf & 31;
    int L = isL ? LL : LG;
    int T = isL ? TMAX : 5;
    const float* w    = isL ? wL : wG;
    const int*   list = isL ? g_blistL : g_blistG;
    const int*   boff = isL ? g_boffL  : g_boffG;
    float*       wt   = isL ? g_wtL    : g_wtG;
    int tid = threadIdx.x;
    if (tid <= T) soff[tid] = boff[b * (TMAX + 1) + tid];
    __syncthreads();
    const int*   lst = list + b * L;
    const float* wf  = w + (size_t)f * L * 8;
    float* o = wt + (size_t)bf * (T * 8);
    int wid = tid >> 5, lane = tid & 31;
    int pg = lane >> 3, k = lane & 7;
    for (int tt = wid; tt < T; tt += 8) {
        int lo = soff[tt], hi = soff[tt + 1];
        float acc = 0.f;
        for (int p = lo + pg; p < hi; p += 4) {
            int c8 = __ldg(&lst[p]);
            acc += __ldg(&wf[c8 + k]);
        }
        acc += __shfl_xor_sync(FULL, acc, 8);
        acc += __shfl_xor_sync(FULL, acc, 16);
        if (lane < 8) o[tt * 8 + k] = acc;
    }
}

// ---------------- RNA: conv-y (fused G+L) ----------------
__global__ void k_convy2(const float* __restrict__ embG, const float* __restrict__ embL,
                         const float* __restrict__ cbG, const float* __restrict__ cbL) {
    __shared__ float swt[TMAX * 8];
    int isL = blockIdx.x < 2048 ? 1 : 0;
    int bf  = isL ? blockIdx.x : (blockIdx.x - 2048);
    int b = bf >> 5, f = bf & 31;
    int T = isL ? TMAX : 5;
    const float* emb = isL ? embL : embG;
    const float* cb  = isL ? cbL  : cbG;
    const float* wt  = isL ? g_wtL : g_wtG;
    float*       y   = isL ? g_yL  : g_yG;
    int t = threadIdx.x;
    const float* src = wt + (size_t)bf * (T * 8);
    for (int i = t; i < T * 8; i += 128) swt[i] = src[i];
    __syncthreads();
    if (t < 121) {
        float acc0 = cb[f], acc1 = 0.f;
        for (int tt = 0; tt < T; tt++) {
            const float* er = emb + tt * EMBD;
            acc0 = fmaf(swt[tt*8+0], er[t+0], acc0);
            acc1 = fmaf(swt[tt*8+1], er[t+1], acc1);
            acc0 = fmaf(swt[tt*8+2], er[t+2], acc0);
            acc1 = fmaf(swt[tt*8+3], er[t+3], acc1);
            acc0 = fmaf(swt[tt*8+4], er[t+4], acc0);
            acc1 = fmaf(swt[tt*8+5], er[t+5], acc1);
            acc0 = fmaf(swt[tt*8+6], er[t+6], acc0);
            acc1 = fmaf(swt[tt*8+7], er[t+7], acc1);
        }
        y[b * FCIN + f * 121 + t] = acc0 + acc1;
    }
}

// ---------------- RNA: fc partials (grid 64x4, atomic into bias-inited out) ----------------
__global__ void k_fc(const float* __restrict__ fw, float* __restrict__ out) {
    __shared__ float sy[FCIN / 4];
    __shared__ float sred[2][EMBD];
    int b = blockIdx.x, ch = blockIdx.y, tid = threadIdx.x;
    int base = ch * (FCIN / 4);
    for (int i = tid; i < FCIN / 4; i += 256)
        sy[i] = 0.5f * (g_yG[b * FCIN + base + i] + g_yL[b * FCIN + base + i]);
    __syncthreads();
    int t = tid & 127, rep = tid >> 7;
    float a0 = 0.f, a1 = 0.f;
    for (int i = rep * 2; i < FCIN / 4; i += 4) {
        a0 = fmaf(sy[i + 0], __ldg(&fw[(base + i + 0) * EMBD + t]), a0);
        a1 = fmaf(sy[i + 1], __ldg(&fw[(base + i + 1) * EMBD + t]), a1);
    }
    sred[rep][t] = a0 + a1;
    __syncthreads();
    if (tid < 128)
        atomicAdd(&out[b * EMBD + tid], sred[0][tid] + sred[1][tid]);
}

// ---------------- launch ----------------
extern "C" void kernel_launch(void* const* d_in, const int* in_sizes, int n_in,
                              void* d_out, int out_size) {
    const float* px   = (const float*)d_in[0];
    const int*   ei   = (const int*)d_in[1];
    const float* pw   = (const float*)d_in[2];
    const int*   pbat = (const int*)d_in[3];
    const int*   rg   = (const int*)d_in[4];
    const int*   rl   = (const int*)d_in[5];
    const float* g1w1 = (const float*)d_in[6];
    const float* g1b1 = (const float*)d_in[7];
    const float* g1w2 = (const float*)d_in[8];
    const float* g1b2 = (const float*)d_in[9];
    const float* g1ew = (const float*)d_in[10];
    const float* g1eb = (const float*)d_in[11];
    const float* g1ep = (const float*)d_in[12];
    const float* gw1  = (const float*)d_in[13];
    const float* gb1  = (const float*)d_in[14];
    const float* gw2  = (const float*)d_in[15];
    const float* gb2  = (const float*)d_in[16];
    const float* gew  = (const float*)d_in[17];
    const float* geb  = (const float*)d_in[18];
    const float* gep  = (const float*)d_in[19];
    const float* bng  = (const float*)d_in[20];
    const float* bnb  = (const float*)d_in[21];
    const float* fxpw = (const float*)d_in[22];
    const float* fxpb = (const float*)d_in[23];
    const float* emb1 = (const float*)d_in[24];
    const float* emb2 = (const float*)d_in[25];
    const float* c1w  = (const float*)d_in[26];
    const float* c1b  = (const float*)d_in[27];
    const float* c2w  = (const float*)d_in[28];
    const float* c2b  = (const float*)d_in[29];
    const float* fxw  = (const float*)d_in[30];
    const float* fxb  = (const float*)d_in[31];
    float* out = (float*)d_out;

    void* offp; cudaGetSymbolAddress(&offp, g_off);

    cudaStream_t s1;
    cudaStreamCreateWithFlags(&s1, cudaStreamNonBlocking);
    cudaEvent_t eF, eJ;
    cudaEventCreateWithFlags(&eF, cudaEventDisableTiming);
    cudaEventCreateWithFlags(&eJ, cudaEventDisableTiming);
    cudaEventRecord(eF, 0);
    cudaStreamWaitEvent(s1, eF, 0);

    // Protein chain on stream 0
    cudaMemsetAsync(offp, 0, (NN + 1) * sizeof(int), 0);   // 0 (memset node)
    k_initB<<<1, 256>>>();                         // 1
    k_padhist<<<1024, 256>>>(px, ei);              // 2
    k_scanAll<<<NBSC, 1024>>>();                   // 3
    k_scatter<<<1024, 256>>>(ei, pw);              // 4
    k_gine33<<<1184, 256>>>(g1w1, g1b1, g1w2, g1b2, g1ew, g1eb, g1ep);
    for (int i = 0; i < 4; i++) {
        k_gine16<<<1184, 256>>>(gw1 + i * 256, gb1 + i * 16,
                                gw2 + i * 256, gb2 + i * 16,
                                gew + i * 16,  geb + i * 16,
                                gep + i, bng + i * 16, bnb + i * 16,
                                pbat, i + 1, i & 1, (i == 3) ? 1 : 0);
    }
    k_head<<<BGR, 128>>>(pbat, bng + 64, bnb + 64, fxpw, fxpb, out);

    // RNA branch on side stream (concurrent with protein chain)
    k_bucket2<<<128, 256, 0, s1>>>(rg, rl, fxb, out);
    k_wtilde4<<<4096, 256, 0, s1>>>(c1w, c2w);
    k_convy2<<<4096, 128, 0, s1>>>(emb1, emb2, c1b, c2b);
    k_fc<<<dim3(BGR, 4), 256, 0, s1>>>(fxw, out);
    cudaEventRecord(eJ, s1);
    cudaStreamWaitEvent(0, eJ, 0);

    cudaStreamDestroy(s1);
    cudaEventDestroy(eF);
    cudaEventDestroy(eJ);
}

// round 17
// speedup vs baseline: 1.0533x; 1.0533x over previous
#include <cuda_runtime.h>

#define NN     100000
#define NE     3200000
#define BGR    64
#define DIM    16
#define NFP    33
#define EMBD   128
#define LG     3000
#define LL     2998
#define NFILT  32
#define FCIN   3872    // 32*121
#define TMAX   65
#define NBSC   98      // scan blocks: 98*1024 >= NN+1
#define FULL   0xffffffffu
#define INVW   (1.0f / 32767.0f)

// ---------------- device scratch (static, no allocation) ----------------
__device__ int      g_off[NN + 1];
__device__ int      g_cur[NN];
__device__ unsigned g_csru[NE];          // (src << 15) | w_q15
__device__ float4   g_pxp[NN * 10];      // padded 40-float rows (160B, sector-aligned)
__device__ float4   g_xb0[NN * 4];       // hidden x fp32 (16 floats per node)
__device__ float4   g_xb1[NN * 4];
__device__ double   g_stats5[5 * 32];    // per-layer: [0:16) sum, [16:32) sumsq
__device__ float    g_pool[BGR * DIM];
__device__ int      g_cnt[BGR];
__device__ int      g_bsum[NBSC];
__device__ int      g_bpref[NBSC];
__device__ int      g_arrive;
__device__ int      g_ready;
__device__ int      g_boffG[BGR * (TMAX + 1)];
__device__ int      g_boffL[BGR * (TMAX + 1)];
__device__ int      g_blistG[BGR * LG];
__device__ int      g_blistL[BGR * LL];
__device__ float    g_wtG[BGR * NFILT * 5 * 8];
__device__ float    g_wtL[BGR * NFILT * TMAX * 8];
__device__ float    g_yG[BGR * FCIN];
__device__ float    g_yL[BGR * FCIN];

// ---------------- init ----------------
__global__ void k_initA() {
    int i  = blockIdx.x * blockDim.x + threadIdx.x;
    int st = gridDim.x * blockDim.x;
    for (int j = i; j <= NN; j += st) g_off[j] = 0;
    if (i < 5 * 32) g_stats5[i] = 0.0;
    if (i == 0) { g_arrive = 0; g_ready = 0; }
    for (int j = i; j < BGR * DIM; j += st) g_pool[j] = 0.f;
}

// ---------------- pad pro_x to 40-float rows + degree histogram, fused ----------------
__global__ void k_padhist(const float* __restrict__ px, const int* __restrict__ ei) {
    int i  = blockIdx.x * blockDim.x + threadIdx.x;
    int st = gridDim.x * blockDim.x;
    float* o = (float*)g_pxp;
    for (int idx = i; idx < NN * 40; idx += st) {
        int n = idx / 40, d = idx - n * 40;
        o[idx] = (d < NFP) ? px[n * NFP + d] : 0.f;
    }
    for (int e = i; e < NE; e += st) atomicAdd(&g_off[ei[NE + e] + 1], 1);
}

// ---------------- single-pass decoupled scan (98 blocks, warp-parallel tail) ----------------
__global__ void k_scanAll() {
    __shared__ int s[1024];
    __shared__ int bpref;
    int t = threadIdx.x;
    int i = blockIdx.x * 1024 + t;
    int v = (i <= NN) ? g_off[i] : 0;
    s[t] = v;
    __syncthreads();
    for (int ofs = 1; ofs < 1024; ofs <<= 1) {
        int add = (t >= ofs) ? s[t - ofs] : 0;
        __syncthreads();
        s[t] += add;
        __syncthreads();
    }
    int myinc = s[t];
    if (t < 32) {
        int ticket = 0;
        if (t == 0) {
            g_bsum[blockIdx.x] = s[1023];
            __threadfence();
            ticket = atomicAdd(&g_arrive, 1);
        }
        ticket = __shfl_sync(FULL, ticket, 0);
        if (ticket == NBSC - 1) {
            int b0 = t * 4;
            int v0 = (b0     < NBSC) ? __ldcg(&g_bsum[b0])     : 0;
            int v1 = (b0 + 1 < NBSC) ? __ldcg(&g_bsum[b0 + 1]) : 0;
            int v2 = (b0 + 2 < NBSC) ? __ldcg(&g_bsum[b0 + 2]) : 0;
            int v3 = (b0 + 3 < NBSC) ? __ldcg(&g_bsum[b0 + 3]) : 0;
            int lsum = v0 + v1 + v2 + v3;
            int pre = lsum;
            #pragma unroll
            for (int ofs = 1; ofs < 32; ofs <<= 1) {
                int up = __shfl_up_sync(FULL, pre, ofs);
                if (t >= ofs) pre += up;
            }
            pre -= lsum;   // exclusive
            if (b0     < NBSC) g_bpref[b0]     = pre;
            if (b0 + 1 < NBSC) g_bpref[b0 + 1] = pre + v0;
            if (b0 + 2 < NBSC) g_bpref[b0 + 2] = pre + v0 + v1;
            if (b0 + 3 < NBSC) g_bpref[b0 + 3] = pre + v0 + v1 + v2;
            __threadfence();
            if (t == 0) atomicExch(&g_ready, 1);
        }
        if (t == 0) {
            while (atomicAdd(&g_ready, 0) == 0) { __nanosleep(64); }
            bpref = __ldcg(&g_bpref[blockIdx.x]);
        }
    }
    __syncthreads();
    if (i <= NN) {
        int fin = myinc + bpref;
        g_off[i] = fin;
        if (i < NN) g_cur[i] = fin;
    }
}

// ---------------- scatter (L2 throughput floor; ILP2) ----------------
__global__ void k_scatter(const int* __restrict__ ei, const float* __restrict__ pw) {
    int i  = blockIdx.x * blockDim.x + threadIdx.x;
    int st = gridDim.x * blockDim.x;
    for (int e = i * 2; e < NE; e += st * 2) {
        int s0 = ei[e],      d0 = ei[NE + e];
        int s1 = ei[e + 1],  d1 = ei[NE + e + 1];
        float w0v = pw[e], w1v = pw[e + 1];
        unsigned q0 = (unsigned)(w0v * 32767.0f + 0.5f);
        unsigned q1 = (unsigned)(w1v * 32767.0f + 0.5f);
        int p0 = atomicAdd(&g_cur[d0], 1);
        int p1 = atomicAdd(&g_cur[d1], 1);
        g_csru[p0] = ((unsigned)s0 << 15) | q0;
        g_csru[p1] = ((unsigned)s1 << 15) | q1;
    }
}

// ---------------- GINE layer 1 (33 -> 16): trip-count loop + split-half MLP (dual acc) ----------------
__global__ void k_gine33(const float* __restrict__ W1, const float* __restrict__ b1,
                         const float* __restrict__ W2, const float* __restrict__ b2,
                         const float* __restrict__ ew, const float* __restrict__ ebv,
                         const float* __restrict__ epsp) {
    __shared__ float sW1[NFP * 16], sW2[256], sb1[16], sb2[16], sc[36], se[36];
    __shared__ float ssum[16], ssq[16];
    int t = threadIdx.x;
    for (int i = t; i < NFP * 16; i += 256) sW1[i] = W1[i];
    for (int i = t; i < 256; i += 256) sW2[i] = W2[i];
    if (t < 16) { sb1[t] = b1[t]; sb2[t] = b2[t]; ssum[t] = 0.f; ssq[t] = 0.f; }
    if (t < 36) { sc[t] = (t < NFP) ? ew[t] : 0.f; se[t] = (t < NFP) ? ebv[t] : 0.f; }
    __syncthreads();
    float ope = 1.f + epsp[0];
    int lane  = t & 31;
    int eslot = lane >> 2, q = lane & 3;
    float cA0 = sc[q*4+0], cA1 = sc[q*4+1], cA2 = sc[q*4+2], cA3 = sc[q*4+3];
    float eA0 = se[q*4+0], eA1 = se[q*4+1], eA2 = se[q*4+2], eA3 = se[q*4+3];
    float cB0 = sc[(q+4)*4+0], cB1 = sc[(q+4)*4+1], cB2 = sc[(q+4)*4+2], cB3 = sc[(q+4)*4+3];
    float eB0 = se[(q+4)*4+0], eB1 = se[(q+4)*4+1], eB2 = se[(q+4)*4+2], eB3 = se[(q+4)*4+3];
    float c32 = sc[32], e32 = se[32];
    int gw = blockIdx.x * 8 + (t >> 5);
    int nw = gridDim.x * 8;
    float lsum = 0.f, lsq = 0.f;
    for (int n = gw; n < NN; n += nw) {
        int beg = g_off[n], end = g_off[n + 1];
        int trips = (end - beg + 7) >> 3;   // warp-uniform
        const float* nrow = (const float*)(g_pxp + n * 10);
        float selfv = __ldg(nrow + lane);
        float self32 = __ldg(nrow + 32);
        float ax=0,ay=0,az=0,aw=0, bx=0,by=0,bz=0,bw=0, a32=0;
        int j = beg + eslot;
        unsigned vc0 = (j < end)     ? __ldg(&g_csru[j])     : 0u;
        unsigned vc1 = (j + 8 < end) ? __ldg(&g_csru[j + 8]) : 0u;
        float4 xa0 = make_float4(0, 0, 0, 0), xb0 = make_float4(0, 0, 0, 0);
        float x320 = 0.f;
        if (j < end) {
            const float4* row = g_pxp + (vc0 >> 15) * 10;
            xa0 = __ldg(row + q);
            xb0 = __ldg(row + q + 4);
            if (q == 0) x320 = __ldg(((const float*)row) + 32);
        }
        for (int it = 0; it < trips; it++) {
            unsigned vc2 = (j + 16 < end) ? __ldg(&g_csru[j + 16]) : 0u;
            float4 xa1 = make_float4(0, 0, 0, 0), xb1 = make_float4(0, 0, 0, 0);
            float x321 = 0.f;
            if (j + 8 < end) {
                const float4* row = g_pxp + (vc1 >> 15) * 10;
                xa1 = __ldg(row + q);
                xb1 = __ldg(row + q + 4);
                if (q == 0) x321 = __ldg(((const float*)row) + 32);
            }
            if (j < end) {
                float wv = (float)(vc0 & 32767u) * INVW;
                ax += fmaxf(xa0.x + fmaf(wv, cA0, eA0), 0.f);
                ay += fmaxf(xa0.y + fmaf(wv, cA1, eA1), 0.f);
                az += fmaxf(xa0.z + fmaf(wv, cA2, eA2), 0.f);
                aw += fmaxf(xa0.w + fmaf(wv, cA3, eA3), 0.f);
                bx += fmaxf(xb0.x + fmaf(wv, cB0, eB0), 0.f);
                by += fmaxf(xb0.y + fmaf(wv, cB1, eB1), 0.f);
                bz += fmaxf(xb0.z + fmaf(wv, cB2, eB2), 0.f);
                bw += fmaxf(xb0.w + fmaf(wv, cB3, eB3), 0.f);
                if (q == 0) a32 += fmaxf(x320 + fmaf(wv, c32, e32), 0.f);
            }
            vc0 = vc1; vc1 = vc2;
            xa0 = xa1; xb0 = xb1; x320 = x321;
            j += 8;
        }
        #pragma unroll
        for (int ofs = 4; ofs < 32; ofs <<= 1) {
            ax += __shfl_xor_sync(FULL, ax, ofs); ay += __shfl_xor_sync(FULL, ay, ofs);
            az += __shfl_xor_sync(FULL, az, ofs); aw += __shfl_xor_sync(FULL, aw, ofs);
            bx += __shfl_xor_sync(FULL, bx, ofs); by += __shfl_xor_sync(FULL, by, ofs);
            bz += __shfl_xor_sync(FULL, bz, ofs); bw += __shfl_xor_sync(FULL, bw, ofs);
            a32 += __shfl_xor_sync(FULL, a32, ofs);
        }
        int srcl = (lane >> 2) & 3;
        float vax = __shfl_sync(FULL, ax, srcl), vay = __shfl_sync(FULL, ay, srcl);
        float vaz = __shfl_sync(FULL, az, srcl), vaw = __shfl_sync(FULL, aw, srcl);
        float vbx = __shfl_sync(FULL, bx, srcl), vby = __shfl_sync(FULL, by, srcl);
        float vbz = __shfl_sync(FULL, bz, srcl), vbw = __shfl_sync(FULL, bw, srcl);
        float gx = (lane >= 16) ? vbx : vax;
        float gy = (lane >= 16) ? vby : vay;
        float gz = (lane >= 16) ? vbz : vaz;
        float gwv = (lane >= 16) ? vbw : vaw;
        float lo = (lane & 1) ? gy : gx;
        float hi = (lane & 1) ? gwv : gz;
        float aggv = (lane & 2) ? hi : lo;
        float agg32 = __shfl_sync(FULL, a32, 0);
        float h   = ope * selfv + aggv;    // dims 0..31 (lane = dim)
        float h32 = ope * self32 + agg32;
        // ---- split-half MLP, dual accumulators ----
        int o = lane & 15;
        int halfsel = lane & 16;
        int dbase = halfsel;
        float tj0 = halfsel ? (h32 * sW1[512 + o]) : sb1[o];
        float tj1 = 0.f;
        #pragma unroll
        for (int d = 0; d < 8; d++) {
            float hd0 = __shfl_sync(FULL, h, dbase + d);
            float hd1 = __shfl_sync(FULL, h, dbase + 8 + d);
            tj0 = fmaf(hd0, sW1[(dbase + d) * 16 + o], tj0);
            tj1 = fmaf(hd1, sW1[(dbase + 8 + d) * 16 + o], tj1);
        }
        float tj = tj0 + tj1;
        tj += __shfl_xor_sync(FULL, tj, 16);
        tj = fmaxf(tj, 0.f);
        int kbase = halfsel ? 8 : 0;
        float oj0 = halfsel ? 0.f : sb2[o];
        float oj1 = 0.f;
        #pragma unroll
        for (int k = 0; k < 4; k++) {
            float td0 = __shfl_sync(FULL, tj, kbase + k);
            float td1 = __shfl_sync(FULL, tj, kbase + 4 + k);
            oj0 = fmaf(td0, sW2[(kbase + k) * 16 + o], oj0);
            oj1 = fmaf(td1, sW2[(kbase + 4 + k) * 16 + o], oj1);
        }
        float oj = oj0 + oj1;
        oj += __shfl_xor_sync(FULL, oj, 16);
        if (lane < 16) {
            float y = fmaxf(oj, 0.f);
            ((float*)g_xb0)[n * DIM + lane] = y;
            lsum += y; lsq += y * y;
        }
    }
    if (lane < 16) { atomicAdd(&ssum[lane], lsum); atomicAdd(&ssq[lane], lsq); }
    __syncthreads();
    if (t < 16) {
        atomicAdd(&g_stats5[t],      (double)ssum[t]);
        atomicAdd(&g_stats5[16 + t], (double)ssq[t]);
    }
}

// ---------------- GINE layers 2..5: 2 nodes/warp, TWO edge chains per lane (MLP 4) ----------------
__global__ void __launch_bounds__(256, 4)
k_gine16(const float* __restrict__ W1, const float* __restrict__ b1,
         const float* __restrict__ W2, const float* __restrict__ b2,
         const float* __restrict__ ew, const float* __restrict__ ebv,
         const float* __restrict__ epsp,
         const float* __restrict__ gamma, const float* __restrict__ beta,
         const int* __restrict__ batch,
         int layer, int flip, int accpool) {
    const float4* xin4 = flip ? g_xb1 : g_xb0;
    float*        xout = (float*)(flip ? g_xb0 : g_xb1);
    const float*  xin  = (const float*)xin4;
    __shared__ float sW1[256], sW2[256], sb1[16], sb2[16], sc[16], se[16], sa[16], sbb[16];
    __shared__ float ssum[16], ssq[16];
    __shared__ float spool[BGR * DIM];
    int t = threadIdx.x;
    for (int i = t; i < 256; i += 256) { sW1[i] = W1[i]; sW2[i] = W2[i]; }
    if (accpool)
        for (int i = t; i < BGR * DIM; i += 256) spool[i] = 0.f;
    if (t < 16) {
        sb1[t] = b1[t]; sb2[t] = b2[t]; sc[t] = ew[t]; se[t] = ebv[t];
        double s = g_stats5[(layer - 1) * 32 + t], qd = g_stats5[(layer - 1) * 32 + 16 + t];
        float mu  = (float)(s / (double)NN);
        float var = (float)(qd / (double)NN) - mu * mu;
        float a   = gamma[t] * rsqrtf(fmaxf(var, 0.f) + 1e-5f);
        sa[t] = a; sbb[t] = beta[t] - mu * a;
        ssum[t] = 0.f; ssq[t] = 0.f;
    }
    __syncthreads();
    float ope = 1.f + epsp[0];
    int lane  = t & 31;
    int l16   = lane & 15;
    int hw    = lane >> 4;
    int hwb   = lane & 16;
    int eslot = l16 >> 2, q = l16 & 3;
    float a0 = sa[q*4+0], a1 = sa[q*4+1], a2 = sa[q*4+2], a3 = sa[q*4+3];
    float p0 = sbb[q*4+0], p1 = sbb[q*4+1], p2 = sbb[q*4+2], p3 = sbb[q*4+3];
    float c0 = sc[q*4+0], c1 = sc[q*4+1], c2 = sc[q*4+2], c3 = sc[q*4+3];
    float e0 = se[q*4+0], e1 = se[q*4+1], e2 = se[q*4+2], e3 = se[q*4+3];
    int gw = blockIdx.x * 8 + (t >> 5);
    int np = gridDim.x * 8;
    float lsum = 0.f, lsq = 0.f;
    for (int p = gw; p < NN / 2; p += np) {
        int n = p * 2 + hw;
        int beg = g_off[n], end = g_off[n + 1];
        int deg = end - beg;
        int degmax = max(deg, __shfl_xor_sync(FULL, deg, 16));
        int trips = (degmax + 7) >> 3;      // warp-uniform, 8 edges/node/iter
        float xn = __ldg(&xin[n * DIM + l16]);   // prefetch self
        float ax = 0.f, ay = 0.f, az = 0.f, aw = 0.f;
        int j = beg + eslot;                // chain A: j, chain B: j+4, stride 8
        unsigned vA0 = (j < end)      ? __ldg(&g_csru[j])      : 0u;
        unsigned vB0 = (j + 4 < end)  ? __ldg(&g_csru[j + 4])  : 0u;
        unsigned vA1 = (j + 8 < end)  ? __ldg(&g_csru[j + 8])  : 0u;
        unsigned vB1 = (j + 12 < end) ? __ldg(&g_csru[j + 12]) : 0u;
        float4 xA0 = make_float4(0, 0, 0, 0), xB0 = make_float4(0, 0, 0, 0);
        if (j < end)     xA0 = __ldg(&xin4[(vA0 >> 15) * 4 + q]);
        if (j + 4 < end) xB0 = __ldg(&xin4[(vB0 >> 15) * 4 + q]);
        for (int it = 0; it < trips; it++) {
            unsigned vA2 = (j + 16 < end) ? __ldg(&g_csru[j + 16]) : 0u;
            unsigned vB2 = (j + 20 < end) ? __ldg(&g_csru[j + 20]) : 0u;
            float4 xA1 = make_float4(0, 0, 0, 0), xB1 = make_float4(0, 0, 0, 0);
            if (j + 8 < end)  xA1 = __ldg(&xin4[(vA1 >> 15) * 4 + q]);
            if (j + 12 < end) xB1 = __ldg(&xin4[(vB1 >> 15) * 4 + q]);
            if (j < end) {
                float wv = (float)(vA0 & 32767u) * INVW;
                ax += fmaxf(fmaf(a0, xA0.x, p0) + fmaf(wv, c0, e0), 0.f);
                ay += fmaxf(fmaf(a1, xA0.y, p1) + fmaf(wv, c1, e1), 0.f);
                az += fmaxf(fmaf(a2, xA0.z, p2) + fmaf(wv, c2, e2), 0.f);
                aw += fmaxf(fmaf(a3, xA0.w, p3) + fmaf(wv, c3, e3), 0.f);
            }
            if (j + 4 < end) {
                float wv = (float)(vB0 & 32767u) * INVW;
                ax += fmaxf(fmaf(a0, xB0.x, p0) + fmaf(wv, c0, e0), 0.f);
                ay += fmaxf(fmaf(a1, xB0.y, p1) + fmaf(wv, c1, e1), 0.f);
                az += fmaxf(fmaf(a2, xB0.z, p2) + fmaf(wv, c2, e2), 0.f);
                aw += fmaxf(fmaf(a3, xB0.w, p3) + fmaf(wv, c3, e3), 0.f);
            }
            vA0 = vA1; vA1 = vA2; xA0 = xA1;
            vB0 = vB1; vB1 = vB2; xB0 = xB1;
            j += 8;
        }
        #pragma unroll
        for (int ofs = 4; ofs < 16; ofs <<= 1) {
            ax += __shfl_xor_sync(FULL, ax, ofs); ay += __shfl_xor_sync(FULL, ay, ofs);
            az += __shfl_xor_sync(FULL, az, ofs); aw += __shfl_xor_sync(FULL, aw, ofs);
        }
        int srcl = hwb + (l16 >> 2);
        float vx = __shfl_sync(FULL, ax, srcl);
        float vy = __shfl_sync(FULL, ay, srcl);
        float vz = __shfl_sync(FULL, az, srcl);
        float vw = __shfl_sync(FULL, aw, srcl);
        float lo = (l16 & 1) ? vy : vx;
        float hi = (l16 & 1) ? vw : vz;
        float aggv = (l16 & 2) ? hi : lo;
        float h = ope * fmaf(sa[l16], xn, sbb[l16]) + aggv;
        float tj0 = sb1[l16], tj1 = 0.f;
        #pragma unroll
        for (int dd = 0; dd < 8; dd++) {
            float hd0 = __shfl_sync(FULL, h, hwb + dd);
            float hd1 = __shfl_sync(FULL, h, hwb + 8 + dd);
            tj0 = fmaf(hd0, sW1[dd * 16 + l16], tj0);
            tj1 = fmaf(hd1, sW1[(8 + dd) * 16 + l16], tj1);
        }
        float tj = fmaxf(tj0 + tj1, 0.f);
        float oj0 = sb2[l16], oj1 = 0.f;
        #pragma unroll
        for (int dd = 0; dd < 8; dd++) {
            float td0 = __shfl_sync(FULL, tj, hwb + dd);
            float td1 = __shfl_sync(FULL, tj, hwb + 8 + dd);
            oj0 = fmaf(td0, sW2[dd * 16 + l16], oj0);
            oj1 = fmaf(td1, sW2[(8 + dd) * 16 + l16], oj1);
        }
        float y = fmaxf(oj0 + oj1, 0.f);
        if (accpool) {
            int bt = __ldg(&batch[n]);
            atomicAdd(&spool[bt * DIM + l16], y);
        } else {
            xout[n * DIM + l16] = y;
        }
        lsum += y; lsq += y * y;
    }
    atomicAdd(&ssum[l16], lsum); atomicAdd(&ssq[l16], lsq);
    __syncthreads();
    if (t < 16) {
        atomicAdd(&g_stats5[layer * 32 + t],      (double)ssum[t]);
        atomicAdd(&g_stats5[layer * 32 + 16 + t], (double)ssq[t]);
    }
    if (accpool)
        for (int i = t; i < BGR * DIM; i += 256) atomicAdd(&g_pool[i], spool[i]);
}

__device__ __forceinline__ int lbound(const int* a, int n, int key) {
    int lo = 0, hi = n;
    while (lo < hi) { int mid = (lo + hi) >> 1; if (a[mid] < key) lo = mid + 1; else hi = mid; }
    return lo;
}

// ---------------- per-graph node counts (side stream; overlapped) ----------------
__global__ void k_cnt(const int* __restrict__ batch) {
    int b = threadIdx.x;
    if (b < BGR) {
        int lo = lbound(batch, NN, b);
        int hi = lbound(batch, NN, b + 1);
        g_cnt[b] = max(hi - lo, 1);
    }
}

// ---------------- head: final BN affine + mean + fc1_xp ----------------
__global__ void k_head(const float* __restrict__ gamma, const float* __restrict__ beta,
                       const float* __restrict__ fw, const float* __restrict__ fb,
                       float* __restrict__ out) {
    __shared__ float sm[16];
    int b = blockIdx.x, t = threadIdx.x;
    if (t < 16) {
        double s = g_stats5[4 * 32 + t], qd = g_stats5[4 * 32 + 16 + t];
        float mu  = (float)(s / (double)NN);
        float var = (float)(qd / (double)NN) - mu * mu;
        float a   = gamma[t] * rsqrtf(fmaxf(var, 0.f) + 1e-5f);
        float bb  = beta[t] - mu * a;
        sm[t] = a * (g_pool[b * DIM + t] / (float)g_cnt[b]) + bb;
    }
    __syncthreads();
    float acc = fb[t];
    #pragma unroll
    for (int dd = 0; dd < 16; dd++) acc += sm[dd] * fw[dd * EMBD + t];
    out[BGR * EMBD + b * EMBD + t] = fmaxf(acc, 0.f);
}

// ---------------- RNA: bucket build (fused G+L) + fc bias init ----------------
__global__ void k_bucket2(const int* __restrict__ tokG, const int* __restrict__ tokL,
                          const float* __restrict__ fb, float* __restrict__ out) {
    __shared__ int cnt[TMAX + 1];
    __shared__ int offs[TMAX + 1];
    int isL = blockIdx.x >> 6;
    int b   = blockIdx.x & 63;
    int L = isL ? LL : LG;
    int T = isL ? TMAX : 5;
    const int* tok  = isL ? tokL : tokG;
    int* list = isL ? g_blistL : g_blistG;
    int* boff = isL ? g_boffL  : g_boffG;
    int t = threadIdx.x;
    if (!isL && t < EMBD) out[b * EMBD + t] = fb[t];   // fc bias init
    if (t <= T) cnt[t] = 0;
    __syncthreads();
    const int* tb = tok + b * L;
    for (int c = t; c < L; c += 256) atomicAdd(&cnt[tb[c]], 1);
    __syncthreads();
    if (t == 0) {
        int acc = 0;
        for (int i = 0; i < T; i++) { offs[i] = acc; acc += cnt[i]; }
        offs[T] = acc;
    }
    __syncthreads();
    if (t <= T) boff[b * (TMAX + 1) + t] = offs[t];
    if (t < T) cnt[t] = offs[t];
    __syncthreads();
    for (int c = t; c < L; c += 256) {
        int pos = atomicAdd(&cnt[tb[c]], 1);
        list[b * L + pos] = c << 3;
    }
}

// ---------------- RNA: W~ gather-sum (fused G+L) ----------------
__global__ void k_wtilde4(const float* __restrict__ wG, const float* __restrict__ wL) {
    __shared__ int soff[TMAX + 1];
    int isL = blockIdx.x < 2048 ? 1 : 0;
    int bf  = isL ? blockIdx.x : (blockIdx.x - 2048);
    int b = bf >> 5, f = bf & 31;
    int L = isL ? LL : LG;
    int T = isL ? TMAX : 5;
    const float* w    = isL ? wL : wG;
    const int*   list = isL ? g_blistL : g_blistG;
    const int*   boff = isL ? g_boffL  : g_boffG;
    float*       wt   = isL ? g_wtL    : g_wtG;
    int tid = threadIdx.x;
    if (tid <= T) soff[tid] = boff[b * (TMAX + 1) + tid];
    __syncthreads();
    const int*   lst = list + b * L;
    const float* wf  = w + (size_t)f * L * 8;
    float* o = wt + (size_t)bf * (T * 8);
    int wid = tid >> 5, lane = tid & 31;
    int pg = lane >> 3, k = lane & 7;
    for (int tt = wid; tt < T; tt += 8) {
        int lo = soff[tt], hi = soff[tt + 1];
        float acc = 0.f;
        for (int p = lo + pg; p < hi; p += 4) {
            int c8 = __ldg(&lst[p]);
            acc += __ldg(&wf[c8 + k]);
        }
        acc += __shfl_xor_sync(FULL, acc, 8);
        acc += __shfl_xor_sync(FULL, acc, 16);
        if (lane < 8) o[tt * 8 + k] = acc;
    }
}

// ---------------- RNA: conv-y (fused G+L) ----------------
__global__ void k_convy2(const float* __restrict__ embG, const float* __restrict__ embL,
                         const float* __restrict__ cbG, const float* __restrict__ cbL) {
    __shared__ float swt[TMAX * 8];
    int isL = blockIdx.x < 2048 ? 1 : 0;
    int bf  = isL ? blockIdx.x : (blockIdx.x - 2048);
    int b = bf >> 5, f = bf & 31;
    int T = isL ? TMAX : 5;
    const float* emb = isL ? embL : embG;
    const float* cb  = isL ? cbL  : cbG;
    const float* wt  = isL ? g_wtL : g_wtG;
    float*       y   = isL ? g_yL  : g_yG;
    int t = threadIdx.x;
    const float* src = wt + (size_t)bf * (T * 8);
    for (int i = t; i < T * 8; i += 128) swt[i] = src[i];
    __syncthreads();
    if (t < 121) {
        float acc0 = cb[f], acc1 = 0.f;
        for (int tt = 0; tt < T; tt++) {
            const float* er = emb + tt * EMBD;
            acc0 = fmaf(swt[tt*8+0], er[t+0], acc0);
            acc1 = fmaf(swt[tt*8+1], er[t+1], acc1);
            acc0 = fmaf(swt[tt*8+2], er[t+2], acc0);
            acc1 = fmaf(swt[tt*8+3], er[t+3], acc1);
            acc0 = fmaf(swt[tt*8+4], er[t+4], acc0);
            acc1 = fmaf(swt[tt*8+5], er[t+5], acc1);
            acc0 = fmaf(swt[tt*8+6], er[t+6], acc0);
            acc1 = fmaf(swt[tt*8+7], er[t+7], acc1);
        }
        y[b * FCIN + f * 121 + t] = acc0 + acc1;
    }
}

// ---------------- RNA: fc partials (grid 64x4, atomic into bias-inited out) ----------------
__global__ void k_fc(const float* __restrict__ fw, float* __restrict__ out) {
    __shared__ float sy[FCIN / 4];
    __shared__ float sred[2][EMBD];
    int b = blockIdx.x, ch = blockIdx.y, tid = threadIdx.x;
    int base = ch * (FCIN / 4);
    for (int i = tid; i < FCIN / 4; i += 256)
        sy[i] = 0.5f * (g_yG[b * FCIN + base + i] + g_yL[b * FCIN + base + i]);
    __syncthreads();
    int t = tid & 127, rep = tid >> 7;
    float a0 = 0.f, a1 = 0.f;
    for (int i = rep * 2; i < FCIN / 4; i += 4) {
        a0 = fmaf(sy[i + 0], __ldg(&fw[(base + i + 0) * EMBD + t]), a0);
        a1 = fmaf(sy[i + 1], __ldg(&fw[(base + i + 1) * EMBD + t]), a1);
    }
    sred[rep][t] = a0 + a1;
    __syncthreads();
    if (tid < 128)
        atomicAdd(&out[b * EMBD + tid], sred[0][tid] + sred[1][tid]);
}

// ---------------- launch ----------------
extern "C" void kernel_launch(void* const* d_in, const int* in_sizes, int n_in,
                              void* d_out, int out_size) {
    const float* px   = (const float*)d_in[0];
    const int*   ei   = (const int*)d_in[1];
    const float* pw   = (const float*)d_in[2];
    const int*   pbat = (const int*)d_in[3];
    const int*   rg   = (const int*)d_in[4];
    const int*   rl   = (const int*)d_in[5];
    const float* g1w1 = (const float*)d_in[6];
    const float* g1b1 = (const float*)d_in[7];
    const float* g1w2 = (const float*)d_in[8];
    const float* g1b2 = (const float*)d_in[9];
    const float* g1ew = (const float*)d_in[10];
    const float* g1eb = (const float*)d_in[11];
    const float* g1ep = (const float*)d_in[12];
    const float* gw1  = (const float*)d_in[13];
    const float* gb1  = (const float*)d_in[14];
    const float* gw2  = (const float*)d_in[15];
    const float* gb2  = (const float*)d_in[16];
    const float* gew  = (const float*)d_in[17];
    const float* geb  = (const float*)d_in[18];
    const float* gep  = (const float*)d_in[19];
    const float* bng  = (const float*)d_in[20];
    const float* bnb  = (const float*)d_in[21];
    const float* fxpw = (const float*)d_in[22];
    const float* fxpb = (const float*)d_in[23];
    const float* emb1 = (const float*)d_in[24];
    const float* emb2 = (const float*)d_in[25];
    const float* c1w  = (const float*)d_in[26];
    const float* c1b  = (const float*)d_in[27];
    const float* c2w  = (const float*)d_in[28];
    const float* c2b  = (const float*)d_in[29];
    const float* fxw  = (const float*)d_in[30];
    const float* fxb  = (const float*)d_in[31];
    float* out = (float*)d_out;

    cudaStream_t s1;
    cudaStreamCreateWithFlags(&s1, cudaStreamNonBlocking);
    cudaEvent_t eF, eJ, eC;
    cudaEventCreateWithFlags(&eF, cudaEventDisableTiming);
    cudaEventCreateWithFlags(&eJ, cudaEventDisableTiming);
    cudaEventCreateWithFlags(&eC, cudaEventDisableTiming);
    cudaEventRecord(eF, 0);
    cudaStreamWaitEvent(s1, eF, 0);

    // Protein chain on stream 0
    k_initA<<<128, 256>>>();                       // 0
    k_padhist<<<1024, 256>>>(px, ei);              // 1
    k_scanAll<<<NBSC, 1024>>>();                   // 2
    k_scatter<<<1024, 256>>>(ei, pw);              // 3 <- clock probe
    k_gine33<<<1184, 256>>>(g1w1, g1b1, g1w2, g1b2, g1ew, g1eb, g1ep);
    for (int i = 0; i < 4; i++) {
        k_gine16<<<1184, 256>>>(gw1 + i * 256, gb1 + i * 16,
                                gw2 + i * 256, gb2 + i * 16,
                                gew + i * 16,  geb + i * 16,
                                gep + i, bng + i * 16, bnb + i * 16,
                                pbat, i + 1, i & 1, (i == 3) ? 1 : 0);
    }

    // RNA branch + graph counts on side stream (concurrent with protein chain)
    k_cnt<<<1, 64, 0, s1>>>(pbat);
    cudaEventRecord(eC, s1);
    k_bucket2<<<128, 256, 0, s1>>>(rg, rl, fxb, out);
    k_wtilde4<<<4096, 256, 0, s1>>>(c1w, c2w);
    k_convy2<<<4096, 128, 0, s1>>>(emb1, emb2, c1b, c2b);
    k_fc<<<dim3(BGR, 4), 256, 0, s1>>>(fxw, out);
    cudaEventRecord(eJ, s1);

    // head needs g_cnt (from side stream) + pool (stream 0)
    cudaStreamWaitEvent(0, eC, 0);
    k_head<<<BGR, 128>>>(bng + 64, bnb + 64, fxpw, fxpb, out);
    cudaStreamWaitEvent(0, eJ, 0);

    cudaStreamDestroy(s1);
    cudaEventDestroy(eF);
    cudaEventDestroy(eJ);
    cudaEventDestroy(eC);
}